// round 12
// baseline (speedup 1.0000x reference)
#include <cuda_runtime.h>
#include <math.h>

#define LMAX 20
#define NM   21           // number of m columns (0..20)
#define KVAL 441          // (LMAX+1)^2
#define RANK_ 256
#define BPTS 16           // points per CTA
#define NPV  (BPTS * 2)   // 32 (point,vector) pairs
#define NTHREADS 1024     // 32 warps: warps 0..20 each own one m-column
#define PV_STRIDE 65      // padded (coprime with 32 banks)

// --------------------------------------------------------------------------
// Compile-time tables (same product-form normd() math as all passing rounds,
// constexpr double + Newton sqrt). Used ONLY in constant expressions below,
// so A/B/seed/c1 become float IMMEDIATES in SASS (no LDC, rt=1 FFMA-imm).
//   Q(m,m)   = seed[m] * pmm
//   Q(m+1,m) = c1[m] * ct * Q(m,m)
//   Q(l,m)   = A(l,m) * ct * Q(l-1,m) - B(l,m) * Q(l-2,m)
// --------------------------------------------------------------------------
struct F2 { float x, y; };
struct Tab {
    F2    AB[NM * NM];
    float seed[NM];
    float c1[NM];
};

constexpr double csqrt(double v) {
    double g = v > 1.0 ? v : 1.0;
    for (int i = 0; i < 100; ++i) g = 0.5 * (g + v / g);
    return g;
}

constexpr double cnormd(int l, int m) {
    // sqrt( (2l+1)/(4pi) * (l-m)!/(l+m)! ) -- product then one divide
    double p = 1.0;
    for (int k = l - m + 1; k <= l + m; ++k) p *= (double)k;  // (l+m)!/(l-m)!
    return csqrt((2.0 * l + 1.0) / (4.0 * 3.14159265358979323846) / p);
}

constexpr Tab make_tab() {
    Tab t{};
    for (int m = 0; m <= LMAX; ++m) {
        double s = cnormd(m, m);
        if (m > 0) s *= 1.4142135623730951;   // sqrt(2) for m != 0 terms
        t.seed[m] = (float)s;
        t.c1[m] = (m < LMAX)
            ? (float)((2.0 * m + 1.0) * cnormd(m + 1, m) / cnormd(m, m))
            : 0.f;
    }
    for (int l = 0; l <= LMAX; ++l)
        for (int m = 0; m <= LMAX; ++m) {
            F2 ab{0.f, 0.f};
            if (l >= m + 2) {
                ab.x = (float)((2.0 * l - 1.0) / (double)(l - m)
                               * cnormd(l, m) / cnormd(l - 1, m));
                ab.y = (float)((double)(l + m - 1) / (double)(l - m)
                               * cnormd(l, m) / cnormd(l - 2, m));
            }
            t.AB[l * NM + m] = ab;
        }
    return t;
}

constexpr Tab k_tab = make_tab();

// Fully-unrolled recurrence rows for column M, l = L..LMAX.
// All coefficients are immediates; all store offsets are immediates.
template<int M, int L>
__device__ __forceinline__ void rows(float ct, float cm, float sv,
                                     float q1, float q2, float* ps) {
    if constexpr (L <= LMAX) {
        constexpr float A = k_tab.AB[L * NM + M].x;
        constexpr float B = k_tab.AB[L * NM + M].y;
        float qn = A * ct * q1 - B * q2;
        ps[L * (L + 1) + M] = qn * cm;
        if constexpr (M > 0) ps[L * (L + 1) - M] = qn * sv;
        rows<M, L + 1>(ct, cm, sv, qn, q1, ps);
    }
}

template<int M>
__device__ __forceinline__ void do_col(const float* pvd, float* ps, float ct) {
    float cm = pvd[1 + M], sv = pvd[22 + M], pm = pvd[43 + M];
    constexpr float S = k_tab.seed[M];
    float q2 = S * pm;                                  // l = M
    ps[M * (M + 1) + M] = q2 * cm;
    if constexpr (M > 0) ps[M * (M + 1) - M] = q2 * sv;
    if constexpr (M < LMAX) {
        constexpr float C = k_tab.c1[M];
        float q1 = C * ct * q2;                         // l = M+1
        ps[(M + 1) * (M + 2) + M] = q1 * cm;
        if constexpr (M > 0) ps[(M + 1) * (M + 2) - M] = q1 * sv;
        rows<M, M + 2>(ct, cm, sv, q1, q2, ps);
    }
}

// --------------------------------------------------------------------------
// Main kernel: one CTA = BPTS points = 32 (point,vector) pairs, 32 warps.
// Phase 0: warp 0, lane = pv: ct + trig/diagonal chains into s_pv.
// Phase 1: lane = pv; warp w (w <= 20) -> column m = w (templated, fully
//          unrolled, immediate coefficients + store offsets). Warps 21..31
//          pass straight to the barrier. Critical path 21 rows (minimum).
// Phase 2: thread t owns rank (t & 255), 4 points; rolled loop (round-8
//          lesson: do NOT batch-unroll the gathers).
// 2 CTAs/SM (89% occupancy) hide phase-0/barrier shadows in L1 traffic.
// --------------------------------------------------------------------------
__global__ __launch_bounds__(NTHREADS, 2) void sh_kernel(
    const float* __restrict__ coords, const int* __restrict__ ri,
    const int* __restrict__ rj, float* __restrict__ out, int npts)
{
    extern __shared__ float smem[];
    float* s_psi = smem;                    // NPV*KVAL
    float* s_pv  = s_psi + NPV * KVAL;      // NPV*PV_STRIDE

    const int t    = threadIdx.x;
    const int warp = t >> 5;
    const int lane = t & 31;
    const int p0   = blockIdx.x * BPTS;

    // Per-thread rank data for phase 2 (identity mapping, coalesced LDG).
    const int rk = t & (RANK_ - 1);
    const int pi = ri[rk];
    const int pj = rj[rk];

    // Phase 0: per (point, vector) trig / diagonal chains (32 threads).
    if (t < NPV) {
        int p = t >> 1, v = t & 1;
        float ct = 0.f, st = 0.f, ca = 1.f, sa = 0.f;
        if (p0 + p < npts) {
            const float* cp = coords + (size_t)(p0 + p) * 6 + v * 3;
            float X = cp[0], Yc = cp[1], Z = cp[2];
            float r = sqrtf(X * X + Yc * Yc + Z * Z);
            ct = Z / r;
            ct = fminf(1.f, fmaxf(-1.f, ct));
            st = sqrtf(fmaxf(0.f, 1.f - ct * ct));     // sin(arccos(ct)) >= 0
            float rxy2 = X * X + Yc * Yc;
            if (rxy2 > 0.f) {                          // atan2(0,0)=0
                float irxy = rsqrtf(rxy2);
                ca = X * irxy; sa = Yc * irxy;
            }
        }
        float* pvd = s_pv + t * PV_STRIDE;
        pvd[0] = ct;
        float cm = 1.f, sv = 0.f, pm = 1.f;
        pvd[1] = cm; pvd[22] = sv; pvd[43] = pm;
        #pragma unroll
        for (int m = 1; m <= LMAX; ++m) {
            float cn = cm * ca - sv * sa;              // cos(m*azim)
            sv = cm * sa + sv * ca;                    // sin(m*azim)
            cm = cn;
            pm *= (1.f - 2.f * (float)m) * st;         // Condon-Shortley diag
            pvd[1 + m] = cm; pvd[22 + m] = sv; pvd[43 + m] = pm;
        }
    }
    __syncthreads();

    // Phase 1: lane = pv; warp w -> column m = w (warps 21..31 idle).
    if (warp <= LMAX && p0 + (lane >> 1) < npts) {
        const float* pvd = s_pv + lane * PV_STRIDE;
        const float  ct  = pvd[0];
        float* ps = s_psi + lane * KVAL;

        switch (warp) {
            case 0:  do_col<0 >(pvd, ps, ct); break;
            case 1:  do_col<1 >(pvd, ps, ct); break;
            case 2:  do_col<2 >(pvd, ps, ct); break;
            case 3:  do_col<3 >(pvd, ps, ct); break;
            case 4:  do_col<4 >(pvd, ps, ct); break;
            case 5:  do_col<5 >(pvd, ps, ct); break;
            case 6:  do_col<6 >(pvd, ps, ct); break;
            case 7:  do_col<7 >(pvd, ps, ct); break;
            case 8:  do_col<8 >(pvd, ps, ct); break;
            case 9:  do_col<9 >(pvd, ps, ct); break;
            case 10: do_col<10>(pvd, ps, ct); break;
            case 11: do_col<11>(pvd, ps, ct); break;
            case 12: do_col<12>(pvd, ps, ct); break;
            case 13: do_col<13>(pvd, ps, ct); break;
            case 14: do_col<14>(pvd, ps, ct); break;
            case 15: do_col<15>(pvd, ps, ct); break;
            case 16: do_col<16>(pvd, ps, ct); break;
            case 17: do_col<17>(pvd, ps, ct); break;
            case 18: do_col<18>(pvd, ps, ct); break;
            case 19: do_col<19>(pvd, ps, ct); break;
            case 20: do_col<20>(pvd, ps, ct); break;
        }
    }
    __syncthreads();

    // Phase 2: rolled loop, four points per thread, coalesced stores.
    for (int p = (t >> 8); p < BPTS; p += 4) {
        int gp = p0 + p;
        if (gp < npts) {
            float a = s_psi[(2 * p)     * KVAL + pi];
            float b = s_psi[(2 * p + 1) * KVAL + pj];
            out[(size_t)gp * RANK_ + rk] = a * b;
        }
    }
}

extern "C" void kernel_launch(void* const* d_in, const int* in_sizes, int n_in,
                              void* d_out, int out_size) {
    const float* coords = (const float*)d_in[0];
    const int*   ri     = (const int*)d_in[1];
    const int*   rj     = (const int*)d_in[2];
    float*       out    = (float*)d_out;
    int npts = in_sizes[0] / 6;

    const size_t SMEM = (size_t)(NPV * KVAL            // psi
                                 + NPV * PV_STRIDE)    // chains
                        * sizeof(float);
    cudaFuncSetAttribute((const void*)sh_kernel,
                         cudaFuncAttributeMaxDynamicSharedMemorySize, (int)SMEM);

    int grid = (npts + BPTS - 1) / BPTS;
    sh_kernel<<<grid, NTHREADS, SMEM>>>(coords, ri, rj, out, npts);
}

// round 13
// speedup vs baseline: 1.4041x; 1.4041x over previous
#include <cuda_runtime.h>
#include <math.h>

#define LMAX 20
#define NM   21           // number of m columns (0..20)
#define KVAL 441          // (LMAX+1)^2
#define RANK_ 256
#define BPTS 16           // points per CTA
#define NPV  (BPTS * 2)   // 32 (point,vector) pairs
#define NTHREADS 512      // 16 warps (round-12 lesson: points/SM is king)
#define Q_STRIDE 5        // per-pv quad stride (coprime with 32 banks)

// --------------------------------------------------------------------------
// Compile-time constants (same product-form normd() math as all passing
// rounds). A/B/c1 and the folded seed become float IMMEDIATES in SASS.
//   Q(m,m)   = Sfold[m] * st^m           (Sfold = seed[m] * prod(1-2k))
//   Q(m+1,m) = c1[m] * ct * Q(m,m)
//   Q(l,m)   = A(l,m) * ct * Q(l-1,m) - B(l,m) * Q(l-2,m)
// --------------------------------------------------------------------------
struct F2 { float x, y; };
struct Tab {
    F2    AB[NM * NM];
    float sfold[NM];
    float c1[NM];
};

constexpr double csqrt(double v) {
    double g = v > 1.0 ? v : 1.0;
    for (int i = 0; i < 100; ++i) g = 0.5 * (g + v / g);
    return g;
}

constexpr double cnormd(int l, int m) {
    // sqrt( (2l+1)/(4pi) * (l-m)!/(l+m)! ) -- product then one divide
    double p = 1.0;
    for (int k = l - m + 1; k <= l + m; ++k) p *= (double)k;  // (l+m)!/(l-m)!
    return csqrt((2.0 * l + 1.0) / (4.0 * 3.14159265358979323846) / p);
}

constexpr Tab make_tab() {
    Tab t{};
    for (int m = 0; m <= LMAX; ++m) {
        double s = cnormd(m, m);
        if (m > 0) s *= 1.4142135623730951;   // sqrt(2) for m != 0 terms
        double cs = 1.0;                      // Condon-Shortley diag product
        for (int k = 1; k <= m; ++k) cs *= (1.0 - 2.0 * k);
        t.sfold[m] = (float)(s * cs);
        t.c1[m] = (m < LMAX)
            ? (float)((2.0 * m + 1.0) * cnormd(m + 1, m) / cnormd(m, m))
            : 0.f;
    }
    for (int l = 0; l <= LMAX; ++l)
        for (int m = 0; m <= LMAX; ++m) {
            F2 ab{0.f, 0.f};
            if (l >= m + 2) {
                ab.x = (float)((2.0 * l - 1.0) / (double)(l - m)
                               * cnormd(l, m) / cnormd(l - 1, m));
                ab.y = (float)((double)(l + m - 1) / (double)(l - m)
                               * cnormd(l, m) / cnormd(l - 2, m));
            }
            t.AB[l * NM + m] = ab;
        }
    return t;
}

constexpr Tab k_tab = make_tab();

// x^M by compile-time binary powering (<=6 FMUL for M<=20).
template<int M>
__device__ __forceinline__ float fpow(float x) {
    if constexpr (M == 0) return 1.f;
    else if constexpr (M == 1) return x;
    else {
        float h = fpow<M / 2>(x * x);
        if constexpr (M & 1) return h * x;
        else return h;
    }
}

// (cr, ci) = (ca + i*sa)^M by compile-time binary powering.
template<int M>
__device__ __forceinline__ void cpow(float ca, float sa, float& cr, float& ci) {
    if constexpr (M == 0) { cr = 1.f; ci = 0.f; }
    else if constexpr (M == 1) { cr = ca; ci = sa; }
    else {
        float hr, hi;
        cpow<M / 2>(ca, sa, hr, hi);
        float sr = hr * hr - hi * hi;     // square
        float si = 2.f * hr * hi;
        if constexpr (M & 1) {
            cr = sr * ca - si * sa;
            ci = sr * sa + si * ca;
        } else { cr = sr; ci = si; }
    }
}

// Fully-unrolled recurrence rows for column M, l = L..LMAX.
// All coefficients are immediates; all store offsets are immediates.
template<int M, int L>
__device__ __forceinline__ void rows(float ct, float cm, float sv,
                                     float q1, float q2, float* ps) {
    if constexpr (L <= LMAX) {
        constexpr float A = k_tab.AB[L * NM + M].x;
        constexpr float B = k_tab.AB[L * NM + M].y;
        float qn = A * ct * q1 - B * q2;
        ps[L * (L + 1) + M] = qn * cm;
        if constexpr (M > 0) ps[L * (L + 1) - M] = qn * sv;
        rows<M, L + 1>(ct, cm, sv, qn, q1, ps);
    }
}

template<int M>
__device__ __forceinline__ void do_col(const float* q, float* ps) {
    const float ct = q[0], st = q[1], ca = q[2], sa = q[3];
    float cm, sv;
    cpow<M>(ca, sa, cm, sv);                            // cos/sin(M*azim)
    constexpr float S = k_tab.sfold[M];
    float q2 = S * fpow<M>(st);                         // l = M
    ps[M * (M + 1) + M] = q2 * cm;
    if constexpr (M > 0) ps[M * (M + 1) - M] = q2 * sv;
    if constexpr (M < LMAX) {
        constexpr float C = k_tab.c1[M];
        float q1 = C * ct * q2;                         // l = M+1
        ps[(M + 1) * (M + 2) + M] = q1 * cm;
        if constexpr (M > 0) ps[(M + 1) * (M + 2) - M] = q1 * sv;
        rows<M, M + 2>(ct, cm, sv, q1, q2, ps);
    }
}

// --------------------------------------------------------------------------
// Main kernel: one CTA = BPTS points = 32 (point,vector) pairs, 16 warps,
// 4 CTAs/SM (57.1 KB smem, 32 regs) = 2048 threads = full occupancy and
// 64 points/SM (round-12 lesson: points/SM, not occ%, is the throughput).
// Phase 0: warp 0, lane = pv: only ct, st, ca, sa into s_q (stride 5).
// Phase 1: lane = pv; warp w -> m=w, warps 7..11 also m=27-w. Per-m trig /
//          diagonal recomputed in registers via compile-time powering.
// Phase 2: thread t owns rank (t & 255); rolled loop (round-8 lesson:
//          do NOT batch-unroll the gathers).
// --------------------------------------------------------------------------
__global__ __launch_bounds__(NTHREADS, 4) void sh_kernel(
    const float* __restrict__ coords, const int* __restrict__ ri,
    const int* __restrict__ rj, float* __restrict__ out, int npts)
{
    extern __shared__ float smem[];
    float* s_psi = smem;                    // NPV*KVAL
    float* s_q   = s_psi + NPV * KVAL;      // NPV*Q_STRIDE

    const int t    = threadIdx.x;
    const int warp = t >> 5;
    const int lane = t & 31;
    const int p0   = blockIdx.x * BPTS;

    // Per-thread rank data for phase 2 (identity mapping, coalesced LDG).
    const int rk = t & (RANK_ - 1);
    const int pi = ri[rk];
    const int pj = rj[rk];

    // Phase 0: per (point, vector) direction quad (32 threads, no chains).
    if (t < NPV) {
        int p = t >> 1, v = t & 1;
        float ct = 0.f, st = 0.f, ca = 1.f, sa = 0.f;
        if (p0 + p < npts) {
            const float* cp = coords + (size_t)(p0 + p) * 6 + v * 3;
            float X = cp[0], Yc = cp[1], Z = cp[2];
            float r = sqrtf(X * X + Yc * Yc + Z * Z);
            ct = Z / r;
            ct = fminf(1.f, fmaxf(-1.f, ct));
            st = sqrtf(fmaxf(0.f, 1.f - ct * ct));     // sin(arccos(ct)) >= 0
            float rxy2 = X * X + Yc * Yc;
            if (rxy2 > 0.f) {                          // atan2(0,0)=0
                float irxy = rsqrtf(rxy2);
                ca = X * irxy; sa = Yc * irxy;
            }
        }
        float* q = s_q + t * Q_STRIDE;
        q[0] = ct; q[1] = st; q[2] = ca; q[3] = sa;
    }
    __syncthreads();

    // Phase 1: lane = pv; warp-uniform templated columns (21 rows critical).
    if (p0 + (lane >> 1) < npts) {
        const float* q = s_q + lane * Q_STRIDE;
        float* ps = s_psi + lane * KVAL;

        switch (warp) {
            case 0:  do_col<0 >(q, ps); break;
            case 1:  do_col<1 >(q, ps); break;
            case 2:  do_col<2 >(q, ps); break;
            case 3:  do_col<3 >(q, ps); break;
            case 4:  do_col<4 >(q, ps); break;
            case 5:  do_col<5 >(q, ps); break;
            case 6:  do_col<6 >(q, ps); break;
            case 7:  do_col<7 >(q, ps); do_col<20>(q, ps); break;
            case 8:  do_col<8 >(q, ps); do_col<19>(q, ps); break;
            case 9:  do_col<9 >(q, ps); do_col<18>(q, ps); break;
            case 10: do_col<10>(q, ps); do_col<17>(q, ps); break;
            case 11: do_col<11>(q, ps); do_col<16>(q, ps); break;
            case 12: do_col<12>(q, ps); break;
            case 13: do_col<13>(q, ps); break;
            case 14: do_col<14>(q, ps); break;
            case 15: do_col<15>(q, ps); break;
        }
    }
    __syncthreads();

    // Phase 2: rolled loop, two point-slices per thread, coalesced stores.
    for (int p = (t >> 8); p < BPTS; p += 2) {
        int gp = p0 + p;
        if (gp < npts) {
            float a = s_psi[(2 * p)     * KVAL + pi];
            float b = s_psi[(2 * p + 1) * KVAL + pj];
            out[(size_t)gp * RANK_ + rk] = a * b;
        }
    }
}

extern "C" void kernel_launch(void* const* d_in, const int* in_sizes, int n_in,
                              void* d_out, int out_size) {
    const float* coords = (const float*)d_in[0];
    const int*   ri     = (const int*)d_in[1];
    const int*   rj     = (const int*)d_in[2];
    float*       out    = (float*)d_out;
    int npts = in_sizes[0] / 6;

    const size_t SMEM = (size_t)(NPV * KVAL            // psi
                                 + NPV * Q_STRIDE)     // direction quads
                        * sizeof(float);               // = 57088 B
    cudaFuncSetAttribute((const void*)sh_kernel,
                         cudaFuncAttributeMaxDynamicSharedMemorySize, (int)SMEM);

    int grid = (npts + BPTS - 1) / BPTS;
    sh_kernel<<<grid, NTHREADS, SMEM>>>(coords, ri, rj, out, npts);
}